// round 14
// baseline (speedup 1.0000x reference)
#include <cuda_runtime.h>
#include <cuda_bf16.h>
#include <cstdint>

#define BATCH 4096
#define NCLS  200
#define NFEAT 512
#define NPROT 6400
#define ALPHA_F 5.0f
#define EPS_F   1e-8f

#define BM 128
#define BN 256
#define KC 64                 // bf16 per K-chunk = 128 bytes/row
#define NCHUNK (NFEAT / KC)   // 8
#define NBLK   (NPROT / BN)   // 25 dist column-blocks (8 classes each)

#define SEL_BLOCKS (BATCH / 8)   // 512

// ---------------- device scratch (no runtime allocation) ----------------
__device__ __align__(16) __nv_bfloat16 g_Xb[(size_t)BATCH * NFEAT];
__device__ __align__(16) __nv_bfloat16 g_Wb[(size_t)NPROT * NFEAT];
__device__ float g_p2[NPROT];
__device__ unsigned long long g_minpack[(size_t)BATCH * NCLS];
__device__ unsigned long long g_partial[(size_t)BATCH * 32];   // [row][nblk], stride 32
__device__ float g_acc[2];
__device__ unsigned int g_done;

// ---------------- helpers ----------------
__device__ __forceinline__ uint32_t smem_u32(const void* p) {
    uint32_t a;
    asm("{ .reg .u64 t; cvta.to.shared.u64 t, %1; cvt.u32.u64 %0, t; }" : "=r"(a) : "l"(p));
    return a;
}
__device__ __forceinline__ void cp16(uint32_t s, const void* g) {
    asm volatile("cp.async.cg.shared.global [%0], [%1], 16;" :: "r"(s), "l"(g));
}
__device__ __forceinline__ void ldsm4(uint32_t* r, uint32_t addr) {
    asm volatile("ldmatrix.sync.aligned.m8n8.x4.shared.b16 {%0,%1,%2,%3}, [%4];"
                 : "=r"(r[0]), "=r"(r[1]), "=r"(r[2]), "=r"(r[3]) : "r"(addr));
}
__device__ __forceinline__ void mma16816(float* c, const uint32_t* a, const uint32_t* b) {
    asm volatile("mma.sync.aligned.m16n8k16.row.col.f32.bf16.bf16.f32 "
                 "{%0,%1,%2,%3}, {%4,%5,%6,%7}, {%8,%9}, {%0,%1,%2,%3};"
                 : "+f"(c[0]), "+f"(c[1]), "+f"(c[2]), "+f"(c[3])
                 : "r"(a[0]), "r"(a[1]), "r"(a[2]), "r"(a[3]), "r"(b[0]), "r"(b[1]));
}
__device__ __forceinline__ unsigned int f2ord(float f) {
    unsigned int u = __float_as_uint(f);
    return (u & 0x80000000u) ? ~u : (u | 0x80000000u);
}
__device__ __forceinline__ unsigned long long umin64(unsigned long long a, unsigned long long b) {
    return a < b ? a : b;
}

// ---------------- merged convert kernel ----------------
// blocks 0..799: one W row per warp (bf16 convert + exact fp32 p2, shfl-only)
// blocks 800..1055: grid-stride bf16 convert of X
#define CONV_WBLKS 800
#define CONV_XBLKS 256

__global__ __launch_bounds__(256) void conv_kernel(const float* __restrict__ X,
                                                   const float* __restrict__ W) {
    const int lane = threadIdx.x & 31;
    const int w = threadIdx.x >> 5;
    int b = blockIdx.x;
    if (b == 0 && threadIdx.x == 0) {
        g_acc[0] = 0.f; g_acc[1] = 0.f; g_done = 0u;   // reset per replay
    }
    if (b < CONV_WBLKS) {
        int p = b * 8 + w;
        const float4* row = reinterpret_cast<const float4*>(W + (size_t)p * NFEAT);
        uint2* dst = reinterpret_cast<uint2*>(g_Wb + (size_t)p * NFEAT);
        float s = 0.f;
        #pragma unroll
        for (int i = 0; i < 4; i++) {
            float4 v = row[i * 32 + lane];
            __nv_bfloat162 lo = __nv_bfloat162(__float2bfloat16_rn(v.x), __float2bfloat16_rn(v.y));
            __nv_bfloat162 hi = __nv_bfloat162(__float2bfloat16_rn(v.z), __float2bfloat16_rn(v.w));
            uint2 pk;
            pk.x = *reinterpret_cast<uint32_t*>(&lo);
            pk.y = *reinterpret_cast<uint32_t*>(&hi);
            dst[i * 32 + lane] = pk;
            s += v.x * v.x + v.y * v.y + v.z * v.z + v.w * v.w;
        }
        #pragma unroll
        for (int o = 16; o; o >>= 1) s += __shfl_down_sync(0xffffffffu, s, o);
        if (lane == 0) g_p2[p] = s;
    } else {
        int idx = (b - CONV_WBLKS) * 256 + threadIdx.x;
        const int total = BATCH * NFEAT / 4;
        const int stride = CONV_XBLKS * 256;
        #pragma unroll
        for (int it = 0; it < total / stride; it++, idx += stride) {
            float4 v = reinterpret_cast<const float4*>(X)[idx];
            __nv_bfloat162 lo = __nv_bfloat162(__float2bfloat16_rn(v.x), __float2bfloat16_rn(v.y));
            __nv_bfloat162 hi = __nv_bfloat162(__float2bfloat16_rn(v.z), __float2bfloat16_rn(v.w));
            uint2 pk;
            pk.x = *reinterpret_cast<uint32_t*>(&lo);
            pk.y = *reinterpret_cast<uint32_t*>(&hi);
            reinterpret_cast<uint2*>(g_Xb)[idx] = pk;
        }
    }
}

// ---------------- fused bf16 HMMA GEMM + per-class argmin (3-stage, PDL) ----------------
// dynamic smem: p2 (1KB); A: 3 x 16KB; B: 3 x 32KB; rowmin: 1KB
#define SM_P2    0
#define SM_A     1024
#define TILE_A   16384
#define TILE_BB  32768
#define SM_B     (1024 + 3 * TILE_A)
#define SM_RM    (1024 + 3 * TILE_A + 3 * TILE_BB)       // 128 x u64
#define SMEM_TOTAL (SM_RM + 1024)                         // 149504

__global__ __launch_bounds__(256, 1) void dist_kernel() {
    extern __shared__ char smem[];
    uint32_t sb = smem_u32(smem);
    const int tid = threadIdx.x;
    const int lane = tid & 31;
    const int wid = tid >> 5;
    const int wm = wid & 1;      // M half (0/1): rows wm*64..+63
    const int wn = wid >> 1;     // N quarter (0..3): cols wn*64..+63 == 2 classes
    const int n0 = blockIdx.x * BN;
    const int m0 = blockIdx.y * BM;

    unsigned long long* s_rowmin = reinterpret_cast<unsigned long long*>(smem + SM_RM);

    // ---- pure-index setup (overlaps conv tail under PDL) ----
    const int li = tid & 7;
    const int r0 = tid >> 3;             // 0..31
    const uint32_t swo = (uint32_t)((li ^ (r0 & 7)) << 4);   // constant per thread
    const __nv_bfloat16* gA = g_Xb + (size_t)(m0 + r0) * NFEAT + li * 8;
    const __nv_bfloat16* gB = g_Wb + (size_t)(n0 + r0) * NFEAT + li * 8;
    uint32_t sA0 = sb + SM_A + r0 * 128 + swo;
    uint32_t sB0 = sb + SM_B + r0 * 128 + swo;

    const int lr = lane & 7;
    const int lm = lane >> 3;
    const int a_rbase = wm * 64 + (lm & 1) * 8 + lr;
    const int a_chi = lm >> 1;
    const int b_rbase = wn * 64 + (lm >> 1) * 8 + lr;
    const int b_chi = lm & 1;

    if (tid < 128) s_rowmin[tid] = ~0ull;

    float acc[4][8][4];
    #pragma unroll
    for (int i = 0; i < 4; i++)
        #pragma unroll
        for (int j = 0; j < 8; j++)
            #pragma unroll
            for (int k = 0; k < 4; k++) acc[i][j][k] = 0.f;

    // wait for conv grid (PDL) before touching its outputs
#if __CUDA_ARCH__ >= 900
    cudaGridDependencySynchronize();
#endif

    // p2 tile -> smem
    reinterpret_cast<float*>(smem + SM_P2)[tid] = g_p2[n0 + tid];

    // prologue: chunks 0,1 -> buffers 0,1
    #pragma unroll
    for (int pc = 0; pc < 2; pc++) {
        #pragma unroll
        for (int it = 0; it < 4; it++)
            cp16(sA0 + pc * TILE_A + it * (32 * 128), gA + pc * KC + (size_t)it * 32 * NFEAT);
        #pragma unroll
        for (int it = 0; it < 8; it++)
            cp16(sB0 + pc * TILE_BB + it * (32 * 128), gB + pc * KC + (size_t)it * 32 * NFEAT);
        asm volatile("cp.async.commit_group;" ::: "memory");
    }

    #pragma unroll 1
    for (int c = 0; c < NCHUNK; c++) {
        if (c < NCHUNK - 1) asm volatile("cp.async.wait_group 1;" ::: "memory");
        else                asm volatile("cp.async.wait_group 0;" ::: "memory");
        __syncthreads();

        // issue chunk c+2 into buffer (c+2)%3
        if (c + 2 < NCHUNK) {
            int nb = (c + 2) % 3;
            const __nv_bfloat16* gA2 = gA + (c + 2) * KC;
            const __nv_bfloat16* gB2 = gB + (c + 2) * KC;
            #pragma unroll
            for (int it = 0; it < 4; it++)
                cp16(sA0 + nb * TILE_A + it * (32 * 128), gA2 + (size_t)it * 32 * NFEAT);
            #pragma unroll
            for (int it = 0; it < 8; it++)
                cp16(sB0 + nb * TILE_BB + it * (32 * 128), gB2 + (size_t)it * 32 * NFEAT);
            asm volatile("cp.async.commit_group;" ::: "memory");
        }

        uint32_t bufA = sb + SM_A + (c % 3) * TILE_A;
        uint32_t bufB = sb + SM_B + (c % 3) * TILE_BB;

        #pragma unroll
        for (int ks = 0; ks < 4; ks++) {
            uint32_t afr[4][4], bfr[4][4];
            #pragma unroll
            for (int i = 0; i < 4; i++) {
                int r = a_rbase + i * 16;
                int ch = ks * 2 + a_chi;
                ldsm4(afr[i], bufA + r * 128 + ((ch ^ (r & 7)) << 4));
            }
            #pragma unroll
            for (int j2 = 0; j2 < 4; j2++) {
                int r = b_rbase + j2 * 16;
                int ch = ks * 2 + b_chi;
                ldsm4(bfr[j2], bufB + r * 128 + ((ch ^ (r & 7)) << 4));
            }
            #pragma unroll
            for (int i = 0; i < 4; i++)
                #pragma unroll
                for (int j = 0; j < 8; j++)
                    mma16816(acc[i][j], afr[i], bfr[j >> 1] + (j & 1) * 2);
        }
    }

    // ensure s_rowmin init visible to all warps before epilogue atomics
    __syncthreads();

    // ---- epilogue: per-(row,class) packed argmin + per-row block partial ----
    const float* sp2 = reinterpret_cast<const float*>(smem + SM_P2);
    const int cls0 = (n0 >> 5) + wn * 2;
    const int colq = 2 * (lane & 3);

    float p2r[8][2];
    #pragma unroll
    for (int j = 0; j < 8; j++) {
        p2r[j][0] = sp2[wn * 64 + j * 8 + colq];
        p2r[j][1] = sp2[wn * 64 + j * 8 + colq + 1];
    }

    #pragma unroll
    for (int i = 0; i < 4; i++) {
        #pragma unroll
        for (int h = 0; h < 2; h++) {          // class within warp tile
            unsigned long long plo = ~0ull, phi = ~0ull;
            #pragma unroll
            for (int q = 0; q < 4; q++) {
                int j = h * 4 + q;
                #pragma unroll
                for (int t = 0; t < 2; t++) {
                    unsigned nidx = (unsigned)(n0 + wn * 64 + j * 8 + colq + t);
                    float p2v = p2r[j][t];
                    float slo = p2v - 2.0f * acc[i][j][t];
                    plo = umin64(plo, ((unsigned long long)f2ord(slo) << 32) | nidx);
                    float shi = p2v - 2.0f * acc[i][j][2 + t];
                    phi = umin64(phi, ((unsigned long long)f2ord(shi) << 32) | nidx);
                }
            }
            #pragma unroll
            for (int o = 1; o <= 2; o <<= 1) {
                plo = umin64(plo, __shfl_xor_sync(0xffffffffu, plo, o));
                phi = umin64(phi, __shfl_xor_sync(0xffffffffu, phi, o));
            }
            if ((lane & 3) == 0) {
                int rl = wm * 64 + i * 16 + (lane >> 2);
                int row = m0 + rl;
                g_minpack[(size_t)row * NCLS + cls0 + h] = plo;
                g_minpack[(size_t)(row + 8) * NCLS + cls0 + h] = phi;
                atomicMin(&s_rowmin[rl], plo);
                atomicMin(&s_rowmin[rl + 8], phi);
            }
        }
    }

    __syncthreads();
    if (tid < 128)
        g_partial[(size_t)(m0 + tid) * 32 + blockIdx.x] = s_rowmin[tid];
}

// ---------------- selection + fused final reduction (PDL, partial-based) ----------------
__global__ __launch_bounds__(256) void select_kernel(const float* __restrict__ X,
                                                     const float* __restrict__ W,
                                                     const int* __restrict__ tgt,
                                                     float* __restrict__ out) {
    const int lane = threadIdx.x & 31;
    const int w = threadIdx.x >> 5;
    const int row = blockIdx.x * 8 + w;

    // independent load + index math
    const int target = tgt[row];
    const int kt = target >> 3;              // dist block containing the target class
    const int tj = target & 7;               // class slot within that block

    // wait for dist grid (PDL) before reading its outputs
#if __CUDA_ARCH__ >= 900
    cudaGridDependencySynchronize();
#endif

    // target-class entry (broadcast load)
    unsigned long long tpk = g_minpack[(size_t)row * NCLS + target];

    // cross-class min: partials of all blocks except kt, plus kt's classes minus target
    unsigned long long best = ~0ull;
    if (lane < NBLK && lane != kt)
        best = g_partial[(size_t)row * 32 + lane];
    if (lane < 8 && lane != tj)
        best = umin64(best, g_minpack[(size_t)row * NCLS + kt * 8 + lane]);
    #pragma unroll
    for (int o = 16; o; o >>= 1)
        best = umin64(best, __shfl_xor_sync(0xffffffffu, best, o));

    int actual_n = (int)(unsigned)(tpk & 0xffffffffull);
    int wrong_n  = (int)(unsigned)(best & 0xffffffffull);

    const float4* xa = reinterpret_cast<const float4*>(X + (size_t)row * NFEAT);
    const float4* pa = reinterpret_cast<const float4*>(W + (size_t)actual_n * NFEAT);
    const float4* pw = reinterpret_cast<const float4*>(W + (size_t)wrong_n  * NFEAT);
    float ts = 0.f, ws = 0.f;
    #pragma unroll
    for (int f = lane; f < NFEAT / 4; f += 32) {
        float4 x = xa[f], a = pa[f], b = pw[f];
        float d;
        d = x.x - a.x; ts += d * d;  d = x.y - a.y; ts += d * d;
        d = x.z - a.z; ts += d * d;  d = x.w - a.w; ts += d * d;
        d = x.x - b.x; ws += d * d;  d = x.y - b.y; ws += d * d;
        d = x.z - b.z; ws += d * d;  d = x.w - b.w; ws += d * d;
    }
    #pragma unroll
    for (int o = 16; o; o >>= 1) {
        ts += __shfl_xor_sync(0xffffffffu, ts, o);
        ws += __shfl_xor_sync(0xffffffffu, ws, o);
    }

    __shared__ float shf[2][8];
    if (lane == 0) { shf[0][w] = ts; shf[1][w] = ws; }
    __syncthreads();
    if (threadIdx.x == 0) {
        float a = 0.f, b = 0.f;
        #pragma unroll
        for (int i = 0; i < 8; i++) { a += shf[0][i]; b += shf[1][i]; }
        atomicAdd(&g_acc[0], a);
        atomicAdd(&g_acc[1], b);
        __threadfence();
        unsigned int ticket = atomicAdd(&g_done, 1u);
        if (ticket == SEL_BLOCKS - 1) {
            float tsum = *((volatile float*)&g_acc[0]);
            float wsum = *((volatile float*)&g_acc[1]);
            float denom = (float)BATCH * (float)NFEAT;
            float tl  = tsum / denom;
            float ntl = wsum / denom;
            out[0] = (1.0f - ALPHA_F) * tl + ALPHA_F * (1.0f / (ntl + EPS_F));
        }
    }
}

extern "C" void kernel_launch(void* const* d_in, const int* in_sizes, int n_in,
                              void* d_out, int out_size) {
    const float* X   = (const float*)d_in[0];   // outputs [4096, 512]
    const float* W   = (const float*)d_in[1];   // clusters [6400, 512]
    const int*   tgt = (const int*)d_in[2];     // target_classes [4096]
    float* out = (float*)d_out;

    cudaFuncSetAttribute(dist_kernel, cudaFuncAttributeMaxDynamicSharedMemorySize, SMEM_TOTAL);

    conv_kernel<<<CONV_WBLKS + CONV_XBLKS, 256>>>(X, W);

    cudaLaunchAttribute pdl[1];
    pdl[0].id = cudaLaunchAttributeProgrammaticStreamSerialization;
    pdl[0].val.programmaticStreamSerializationAllowed = 1;

    {
        cudaLaunchConfig_t cfg = {};
        cfg.gridDim = dim3(NBLK, BATCH / BM);   // (25, 32)
        cfg.blockDim = dim3(256);
        cfg.dynamicSmemBytes = SMEM_TOTAL;
        cfg.attrs = pdl;
        cfg.numAttrs = 1;
        cudaLaunchKernelEx(&cfg, dist_kernel);
    }
    {
        cudaLaunchConfig_t cfg = {};
        cfg.gridDim = dim3(SEL_BLOCKS);
        cfg.blockDim = dim3(256);
        cfg.attrs = pdl;
        cfg.numAttrs = 1;
        cudaLaunchKernelEx(&cfg, select_kernel, X, W, tgt, out);
    }
}

// round 15
// speedup vs baseline: 1.1092x; 1.1092x over previous
#include <cuda_runtime.h>
#include <cuda_bf16.h>
#include <cstdint>

#define BATCH 4096
#define NCLS  200
#define NFEAT 512
#define NPROT 6400
#define ALPHA_F 5.0f
#define EPS_F   1e-8f

#define BM 128
#define BN 256
#define KC 64                 // bf16 per K-chunk = 128 bytes/row
#define NCHUNK (NFEAT / KC)   // 8

#define SEL_BLOCKS (BATCH / 8)   // 512

// ---------------- device scratch (no runtime allocation) ----------------
__device__ __align__(16) __nv_bfloat16 g_Xb[(size_t)BATCH * NFEAT];
__device__ __align__(16) __nv_bfloat16 g_Wb[(size_t)NPROT * NFEAT];
__device__ float g_p2[NPROT];
__device__ unsigned long long g_minpack[(size_t)BATCH * NCLS];
__device__ float g_acc[2];
__device__ unsigned int g_done;

// ---------------- helpers ----------------
__device__ __forceinline__ uint32_t smem_u32(const void* p) {
    uint32_t a;
    asm("{ .reg .u64 t; cvta.to.shared.u64 t, %1; cvt.u32.u64 %0, t; }" : "=r"(a) : "l"(p));
    return a;
}
__device__ __forceinline__ void cp16(uint32_t s, const void* g) {
    asm volatile("cp.async.cg.shared.global [%0], [%1], 16;" :: "r"(s), "l"(g));
}
__device__ __forceinline__ void ldsm4(uint32_t* r, uint32_t addr) {
    asm volatile("ldmatrix.sync.aligned.m8n8.x4.shared.b16 {%0,%1,%2,%3}, [%4];"
                 : "=r"(r[0]), "=r"(r[1]), "=r"(r[2]), "=r"(r[3]) : "r"(addr));
}
__device__ __forceinline__ void mma16816(float* c, const uint32_t* a, const uint32_t* b) {
    asm volatile("mma.sync.aligned.m16n8k16.row.col.f32.bf16.bf16.f32 "
                 "{%0,%1,%2,%3}, {%4,%5,%6,%7}, {%8,%9}, {%0,%1,%2,%3};"
                 : "+f"(c[0]), "+f"(c[1]), "+f"(c[2]), "+f"(c[3])
                 : "r"(a[0]), "r"(a[1]), "r"(a[2]), "r"(a[3]), "r"(b[0]), "r"(b[1]));
}
__device__ __forceinline__ unsigned int f2ord(float f) {
    unsigned int u = __float_as_uint(f);
    return (u & 0x80000000u) ? ~u : (u | 0x80000000u);
}
__device__ __forceinline__ unsigned long long umin64(unsigned long long a, unsigned long long b) {
    return a < b ? a : b;
}

// ---------------- merged convert kernel ----------------
// blocks 0..799: one W row per warp (bf16 convert + exact fp32 p2, shfl-only)
// blocks 800..1055: grid-stride bf16 convert of X
#define CONV_WBLKS 800
#define CONV_XBLKS 256

__global__ __launch_bounds__(256) void conv_kernel(const float* __restrict__ X,
                                                   const float* __restrict__ W) {
    const int lane = threadIdx.x & 31;
    const int w = threadIdx.x >> 5;
    int b = blockIdx.x;
    if (b == 0 && threadIdx.x == 0) {
        g_acc[0] = 0.f; g_acc[1] = 0.f; g_done = 0u;   // reset per replay
    }
    if (b < CONV_WBLKS) {
        int p = b * 8 + w;
        const float4* row = reinterpret_cast<const float4*>(W + (size_t)p * NFEAT);
        uint2* dst = reinterpret_cast<uint2*>(g_Wb + (size_t)p * NFEAT);
        float s = 0.f;
        #pragma unroll
        for (int i = 0; i < 4; i++) {
            float4 v = row[i * 32 + lane];
            __nv_bfloat162 lo = __nv_bfloat162(__float2bfloat16_rn(v.x), __float2bfloat16_rn(v.y));
            __nv_bfloat162 hi = __nv_bfloat162(__float2bfloat16_rn(v.z), __float2bfloat16_rn(v.w));
            uint2 pk;
            pk.x = *reinterpret_cast<uint32_t*>(&lo);
            pk.y = *reinterpret_cast<uint32_t*>(&hi);
            dst[i * 32 + lane] = pk;
            s += v.x * v.x + v.y * v.y + v.z * v.z + v.w * v.w;
        }
        #pragma unroll
        for (int o = 16; o; o >>= 1) s += __shfl_down_sync(0xffffffffu, s, o);
        if (lane == 0) g_p2[p] = s;
    } else {
        int idx = (b - CONV_WBLKS) * 256 + threadIdx.x;
        const int total = BATCH * NFEAT / 4;
        const int stride = CONV_XBLKS * 256;
        #pragma unroll
        for (int it = 0; it < total / stride; it++, idx += stride) {
            float4 v = reinterpret_cast<const float4*>(X)[idx];
            __nv_bfloat162 lo = __nv_bfloat162(__float2bfloat16_rn(v.x), __float2bfloat16_rn(v.y));
            __nv_bfloat162 hi = __nv_bfloat162(__float2bfloat16_rn(v.z), __float2bfloat16_rn(v.w));
            uint2 pk;
            pk.x = *reinterpret_cast<uint32_t*>(&lo);
            pk.y = *reinterpret_cast<uint32_t*>(&hi);
            reinterpret_cast<uint2*>(g_Xb)[idx] = pk;
        }
    }
}

// ---------------- fused bf16 HMMA GEMM + per-class argmin (3-stage, PDL) ----------------
// dynamic smem: p2 (1KB); A: 3 x 16KB; B: 3 x 32KB
#define SM_P2    0
#define SM_A     1024
#define TILE_A   16384
#define TILE_BB  32768
#define SM_B     (1024 + 3 * TILE_A)
#define SMEM_TOTAL (1024 + 3 * TILE_A + 3 * TILE_BB)   // 148480

__global__ __launch_bounds__(256, 1) void dist_kernel() {
    extern __shared__ char smem[];
    uint32_t sb = smem_u32(smem);
    const int tid = threadIdx.x;
    const int lane = tid & 31;
    const int wid = tid >> 5;
    const int wm = wid & 1;      // M half (0/1): rows wm*64..+63
    const int wn = wid >> 1;     // N quarter (0..3): cols wn*64..+63 == 2 classes
    const int n0 = blockIdx.x * BN;
    const int m0 = blockIdx.y * BM;

    // ---- pure-index setup (overlaps conv tail under PDL) ----
    const int li = tid & 7;
    const int r0 = tid >> 3;             // 0..31
    const uint32_t swo = (uint32_t)((li ^ (r0 & 7)) << 4);   // constant per thread
    const __nv_bfloat16* gA = g_Xb + (size_t)(m0 + r0) * NFEAT + li * 8;
    const __nv_bfloat16* gB = g_Wb + (size_t)(n0 + r0) * NFEAT + li * 8;
    uint32_t sA0 = sb + SM_A + r0 * 128 + swo;
    uint32_t sB0 = sb + SM_B + r0 * 128 + swo;

    const int lr = lane & 7;
    const int lm = lane >> 3;
    const int a_rbase = wm * 64 + (lm & 1) * 8 + lr;
    const int a_chi = lm >> 1;
    const int b_rbase = wn * 64 + (lm >> 1) * 8 + lr;
    const int b_chi = lm & 1;

    float acc[4][8][4];
    #pragma unroll
    for (int i = 0; i < 4; i++)
        #pragma unroll
        for (int j = 0; j < 8; j++)
            #pragma unroll
            for (int k = 0; k < 4; k++) acc[i][j][k] = 0.f;

    // wait for conv grid (PDL) before touching its outputs
#if __CUDA_ARCH__ >= 900
    cudaGridDependencySynchronize();
#endif

    // p2 tile -> smem
    reinterpret_cast<float*>(smem + SM_P2)[tid] = g_p2[n0 + tid];

    // prologue: chunks 0,1 -> buffers 0,1
    #pragma unroll
    for (int pc = 0; pc < 2; pc++) {
        #pragma unroll
        for (int it = 0; it < 4; it++)
            cp16(sA0 + pc * TILE_A + it * (32 * 128), gA + pc * KC + (size_t)it * 32 * NFEAT);
        #pragma unroll
        for (int it = 0; it < 8; it++)
            cp16(sB0 + pc * TILE_BB + it * (32 * 128), gB + pc * KC + (size_t)it * 32 * NFEAT);
        asm volatile("cp.async.commit_group;" ::: "memory");
    }

    #pragma unroll 1
    for (int c = 0; c < NCHUNK; c++) {
        if (c < NCHUNK - 1) asm volatile("cp.async.wait_group 1;" ::: "memory");
        else                asm volatile("cp.async.wait_group 0;" ::: "memory");
        __syncthreads();

        // issue chunk c+2 into buffer (c+2)%3
        if (c + 2 < NCHUNK) {
            int nb = (c + 2) % 3;
            const __nv_bfloat16* gA2 = gA + (c + 2) * KC;
            const __nv_bfloat16* gB2 = gB + (c + 2) * KC;
            #pragma unroll
            for (int it = 0; it < 4; it++)
                cp16(sA0 + nb * TILE_A + it * (32 * 128), gA2 + (size_t)it * 32 * NFEAT);
            #pragma unroll
            for (int it = 0; it < 8; it++)
                cp16(sB0 + nb * TILE_BB + it * (32 * 128), gB2 + (size_t)it * 32 * NFEAT);
            asm volatile("cp.async.commit_group;" ::: "memory");
        }

        uint32_t bufA = sb + SM_A + (c % 3) * TILE_A;
        uint32_t bufB = sb + SM_B + (c % 3) * TILE_BB;

        #pragma unroll
        for (int ks = 0; ks < 4; ks++) {
            uint32_t afr[4][4], bfr[4][4];
            #pragma unroll
            for (int i = 0; i < 4; i++) {
                int r = a_rbase + i * 16;
                int ch = ks * 2 + a_chi;
                ldsm4(afr[i], bufA + r * 128 + ((ch ^ (r & 7)) << 4));
            }
            #pragma unroll
            for (int j2 = 0; j2 < 4; j2++) {
                int r = b_rbase + j2 * 16;
                int ch = ks * 2 + b_chi;
                ldsm4(bfr[j2], bufB + r * 128 + ((ch ^ (r & 7)) << 4));
            }
            #pragma unroll
            for (int i = 0; i < 4; i++)
                #pragma unroll
                for (int j = 0; j < 8; j++)
                    mma16816(acc[i][j], afr[i], bfr[j >> 1] + (j & 1) * 2);
        }
    }

    // ---- epilogue: per-(row,class) packed argmin, plain store ----
    const float* sp2 = reinterpret_cast<const float*>(smem + SM_P2);
    const int cls0 = (n0 >> 5) + wn * 2;
    const int colq = 2 * (lane & 3);

    float p2r[8][2];
    #pragma unroll
    for (int j = 0; j < 8; j++) {
        p2r[j][0] = sp2[wn * 64 + j * 8 + colq];
        p2r[j][1] = sp2[wn * 64 + j * 8 + colq + 1];
    }

    #pragma unroll
    for (int i = 0; i < 4; i++) {
        #pragma unroll
        for (int h = 0; h < 2; h++) {          // class within warp tile
            unsigned long long plo = ~0ull, phi = ~0ull;
            #pragma unroll
            for (int q = 0; q < 4; q++) {
                int j = h * 4 + q;
                #pragma unroll
                for (int t = 0; t < 2; t++) {
                    unsigned nidx = (unsigned)(n0 + wn * 64 + j * 8 + colq + t);
                    float p2v = p2r[j][t];
                    float slo = p2v - 2.0f * acc[i][j][t];
                    plo = umin64(plo, ((unsigned long long)f2ord(slo) << 32) | nidx);
                    float shi = p2v - 2.0f * acc[i][j][2 + t];
                    phi = umin64(phi, ((unsigned long long)f2ord(shi) << 32) | nidx);
                }
            }
            #pragma unroll
            for (int o = 1; o <= 2; o <<= 1) {
                plo = umin64(plo, __shfl_xor_sync(0xffffffffu, plo, o));
                phi = umin64(phi, __shfl_xor_sync(0xffffffffu, phi, o));
            }
            if ((lane & 3) == 0) {
                int row = m0 + wm * 64 + i * 16 + (lane >> 2);
                g_minpack[(size_t)row * NCLS + cls0 + h] = plo;
                g_minpack[(size_t)(row + 8) * NCLS + cls0 + h] = phi;
            }
        }
    }
}

// ---------------- selection + fused final reduction (PDL) ----------------
__global__ __launch_bounds__(256) void select_kernel(const float* __restrict__ X,
                                                     const float* __restrict__ W,
                                                     const int* __restrict__ tgt,
                                                     float* __restrict__ out) {
    const int lane = threadIdx.x & 31;
    const int w = threadIdx.x >> 5;
    const int row = blockIdx.x * 8 + w;

    // independent load (input tensor, not produced by dist) + index math
    const int target = tgt[row];
    const unsigned long long* mp = g_minpack + (size_t)row * NCLS;

    // wait for dist grid (PDL) before reading minpack
#if __CUDA_ARCH__ >= 900
    cudaGridDependencySynchronize();
#endif

    unsigned long long best = ~0ull, tpk = ~0ull;
    #pragma unroll
    for (int c = lane; c < NCLS; c += 32) {
        unsigned long long v = mp[c];
        if (c == target) tpk = v;
        else best = umin64(best, v);
    }
    #pragma unroll
    for (int o = 16; o; o >>= 1) {
        best = umin64(best, __shfl_xor_sync(0xffffffffu, best, o));
        tpk  = umin64(tpk,  __shfl_xor_sync(0xffffffffu, tpk,  o));
    }

    int actual_n = (int)(unsigned)(tpk & 0xffffffffull);
    int wrong_n  = (int)(unsigned)(best & 0xffffffffull);

    const float4* xa = reinterpret_cast<const float4*>(X + (size_t)row * NFEAT);
    const float4* pa = reinterpret_cast<const float4*>(W + (size_t)actual_n * NFEAT);
    const float4* pw = reinterpret_cast<const float4*>(W + (size_t)wrong_n  * NFEAT);
    float ts = 0.f, ws = 0.f;
    #pragma unroll
    for (int f = lane; f < NFEAT / 4; f += 32) {
        float4 x = xa[f], a = pa[f], b = pw[f];
        float d;
        d = x.x - a.x; ts += d * d;  d = x.y - a.y; ts += d * d;
        d = x.z - a.z; ts += d * d;  d = x.w - a.w; ts += d * d;
        d = x.x - b.x; ws += d * d;  d = x.y - b.y; ws += d * d;
        d = x.z - b.z; ws += d * d;  d = x.w - b.w; ws += d * d;
    }
    #pragma unroll
    for (int o = 16; o; o >>= 1) {
        ts += __shfl_xor_sync(0xffffffffu, ts, o);
        ws += __shfl_xor_sync(0xffffffffu, ws, o);
    }

    __shared__ float shf[2][8];
    if (lane == 0) { shf[0][w] = ts; shf[1][w] = ws; }
    __syncthreads();
    if (threadIdx.x == 0) {
        float a = 0.f, b = 0.f;
        #pragma unroll
        for (int i = 0; i < 8; i++) { a += shf[0][i]; b += shf[1][i]; }
        atomicAdd(&g_acc[0], a);
        atomicAdd(&g_acc[1], b);
        __threadfence();
        unsigned int ticket = atomicAdd(&g_done, 1u);
        if (ticket == SEL_BLOCKS - 1) {
            float tsum = *((volatile float*)&g_acc[0]);
            float wsum = *((volatile float*)&g_acc[1]);
            float denom = (float)BATCH * (float)NFEAT;
            float tl  = tsum / denom;
            float ntl = wsum / denom;
            out[0] = (1.0f - ALPHA_F) * tl + ALPHA_F * (1.0f / (ntl + EPS_F));
        }
    }
}

extern "C" void kernel_launch(void* const* d_in, const int* in_sizes, int n_in,
                              void* d_out, int out_size) {
    const float* X   = (const float*)d_in[0];   // outputs [4096, 512]
    const float* W   = (const float*)d_in[1];   // clusters [6400, 512]
    const int*   tgt = (const int*)d_in[2];     // target_classes [4096]
    float* out = (float*)d_out;

    cudaFuncSetAttribute(dist_kernel, cudaFuncAttributeMaxDynamicSharedMemorySize, SMEM_TOTAL);

    conv_kernel<<<CONV_WBLKS + CONV_XBLKS, 256>>>(X, W);

    // PDL attribute: allow overlap with predecessor's tail; the kernel itself
    // gates dependent loads via cudaGridDependencySynchronize().
    cudaLaunchAttribute pdl[1];
    pdl[0].id = cudaLaunchAttributeProgrammaticStreamSerialization;
    pdl[0].val.programmaticStreamSerializationAllowed = 1;

    {
        cudaLaunchConfig_t cfg = {};
        cfg.gridDim = dim3(NPROT / BN, BATCH / BM);   // (25, 32)
        cfg.blockDim = dim3(256);
        cfg.dynamicSmemBytes = SMEM_TOTAL;
        cfg.attrs = pdl;
        cfg.numAttrs = 1;
        cudaLaunchKernelEx(&cfg, dist_kernel);
    }
    {
        cudaLaunchConfig_t cfg = {};
        cfg.gridDim = dim3(SEL_BLOCKS);
        cfg.blockDim = dim3(256);
        cfg.attrs = pdl;
        cfg.numAttrs = 1;
        cudaLaunchKernelEx(&cfg, select_kernel, X, W, tgt, out);
    }
}

// round 16
// speedup vs baseline: 1.1160x; 1.0061x over previous
#include <cuda_runtime.h>
#include <cuda_bf16.h>
#include <cstdint>

#define BATCH 4096
#define NCLS  200
#define NFEAT 512
#define NPROT 6400
#define ALPHA_F 5.0f
#define EPS_F   1e-8f

#define BM 128
#define BN 256
#define KC 64                 // bf16 per K-chunk = 128 bytes/row
#define NCHUNK (NFEAT / KC)   // 8

#define SEL_BLOCKS (BATCH / 8)   // 512

// ---------------- device scratch (no runtime allocation) ----------------
__device__ __align__(16) __nv_bfloat16 g_Xb[(size_t)BATCH * NFEAT];
__device__ __align__(16) __nv_bfloat16 g_Wb[(size_t)NPROT * NFEAT];
__device__ float g_p2[NPROT];
__device__ unsigned long long g_minpack[(size_t)BATCH * NCLS];
__device__ float g_acc[2];
__device__ unsigned int g_done;

// ---------------- helpers ----------------
__device__ __forceinline__ uint32_t smem_u32(const void* p) {
    uint32_t a;
    asm("{ .reg .u64 t; cvta.to.shared.u64 t, %1; cvt.u32.u64 %0, t; }" : "=r"(a) : "l"(p));
    return a;
}
__device__ __forceinline__ void cp16(uint32_t s, const void* g) {
    asm volatile("cp.async.cg.shared.global [%0], [%1], 16;" :: "r"(s), "l"(g));
}
__device__ __forceinline__ void ldsm4(uint32_t* r, uint32_t addr) {
    asm volatile("ldmatrix.sync.aligned.m8n8.x4.shared.b16 {%0,%1,%2,%3}, [%4];"
                 : "=r"(r[0]), "=r"(r[1]), "=r"(r[2]), "=r"(r[3]) : "r"(addr));
}
__device__ __forceinline__ void mma16816(float* c, const uint32_t* a, const uint32_t* b) {
    asm volatile("mma.sync.aligned.m16n8k16.row.col.f32.bf16.bf16.f32 "
                 "{%0,%1,%2,%3}, {%4,%5,%6,%7}, {%8,%9}, {%0,%1,%2,%3};"
                 : "+f"(c[0]), "+f"(c[1]), "+f"(c[2]), "+f"(c[3])
                 : "r"(a[0]), "r"(a[1]), "r"(a[2]), "r"(a[3]), "r"(b[0]), "r"(b[1]));
}
__device__ __forceinline__ unsigned int f2ord(float f) {
    unsigned int u = __float_as_uint(f);
    return (u & 0x80000000u) ? ~u : (u | 0x80000000u);
}
__device__ __forceinline__ unsigned long long umin64(unsigned long long a, unsigned long long b) {
    return a < b ? a : b;
}

// ---------------- merged convert kernel ----------------
// blocks 0..799: one W row per warp (bf16 convert + exact fp32 p2, shfl-only)
// blocks 800..1823: grid-stride bf16 convert of X (2 iterations per thread)
#define CONV_WBLKS 800
#define CONV_XBLKS 1024

__global__ __launch_bounds__(256) void conv_kernel(const float* __restrict__ X,
                                                   const float* __restrict__ W) {
    const int lane = threadIdx.x & 31;
    const int w = threadIdx.x >> 5;
    int b = blockIdx.x;
    if (b == 0 && threadIdx.x == 0) {
        g_acc[0] = 0.f; g_acc[1] = 0.f; g_done = 0u;   // reset per replay
    }
    if (b < CONV_WBLKS) {
        int p = b * 8 + w;
        const float4* row = reinterpret_cast<const float4*>(W + (size_t)p * NFEAT);
        uint2* dst = reinterpret_cast<uint2*>(g_Wb + (size_t)p * NFEAT);
        float s = 0.f;
        #pragma unroll
        for (int i = 0; i < 4; i++) {
            float4 v = row[i * 32 + lane];
            __nv_bfloat162 lo = __nv_bfloat162(__float2bfloat16_rn(v.x), __float2bfloat16_rn(v.y));
            __nv_bfloat162 hi = __nv_bfloat162(__float2bfloat16_rn(v.z), __float2bfloat16_rn(v.w));
            uint2 pk;
            pk.x = *reinterpret_cast<uint32_t*>(&lo);
            pk.y = *reinterpret_cast<uint32_t*>(&hi);
            dst[i * 32 + lane] = pk;
            s += v.x * v.x + v.y * v.y + v.z * v.z + v.w * v.w;
        }
        #pragma unroll
        for (int o = 16; o; o >>= 1) s += __shfl_down_sync(0xffffffffu, s, o);
        if (lane == 0) g_p2[p] = s;
    } else {
        int idx = (b - CONV_WBLKS) * 256 + threadIdx.x;
        const int total = BATCH * NFEAT / 4;           // 524288 float4s
        const int stride = CONV_XBLKS * 256;           // 262144
        #pragma unroll
        for (int it = 0; it < total / stride; it++, idx += stride) {
            float4 v = reinterpret_cast<const float4*>(X)[idx];
            __nv_bfloat162 lo = __nv_bfloat162(__float2bfloat16_rn(v.x), __float2bfloat16_rn(v.y));
            __nv_bfloat162 hi = __nv_bfloat162(__float2bfloat16_rn(v.z), __float2bfloat16_rn(v.w));
            uint2 pk;
            pk.x = *reinterpret_cast<uint32_t*>(&lo);
            pk.y = *reinterpret_cast<uint32_t*>(&hi);
            reinterpret_cast<uint2*>(g_Xb)[idx] = pk;
        }
    }
}

// ---------------- fused bf16 HMMA GEMM + per-class argmin (3-stage, PDL) ----------------
// dynamic smem: p2 (1KB); A: 3 x 16KB; B: 3 x 32KB
#define SM_P2    0
#define SM_A     1024
#define TILE_A   16384
#define TILE_BB  32768
#define SM_B     (1024 + 3 * TILE_A)
#define SMEM_TOTAL (1024 + 3 * TILE_A + 3 * TILE_BB)   // 148480

__global__ __launch_bounds__(256, 1) void dist_kernel() {
    extern __shared__ char smem[];
    uint32_t sb = smem_u32(smem);
    const int tid = threadIdx.x;
    const int lane = tid & 31;
    const int wid = tid >> 5;
    const int wm = wid & 1;      // M half (0/1): rows wm*64..+63
    const int wn = wid >> 1;     // N quarter (0..3): cols wn*64..+63 == 2 classes
    const int n0 = blockIdx.x * BN;
    const int m0 = blockIdx.y * BM;

    // ---- pure-index setup (overlaps conv tail under PDL) ----
    const int li = tid & 7;
    const int r0 = tid >> 3;             // 0..31
    const uint32_t swo = (uint32_t)((li ^ (r0 & 7)) << 4);   // constant per thread
    const __nv_bfloat16* gA = g_Xb + (size_t)(m0 + r0) * NFEAT + li * 8;
    const __nv_bfloat16* gB = g_Wb + (size_t)(n0 + r0) * NFEAT + li * 8;
    uint32_t sA0 = sb + SM_A + r0 * 128 + swo;
    uint32_t sB0 = sb + SM_B + r0 * 128 + swo;

    const int lr = lane & 7;
    const int lm = lane >> 3;
    const int a_rbase = wm * 64 + (lm & 1) * 8 + lr;
    const int a_chi = lm >> 1;
    const int b_rbase = wn * 64 + (lm >> 1) * 8 + lr;
    const int b_chi = lm & 1;

    float acc[4][8][4];
    #pragma unroll
    for (int i = 0; i < 4; i++)
        #pragma unroll
        for (int j = 0; j < 8; j++)
            #pragma unroll
            for (int k = 0; k < 4; k++) acc[i][j][k] = 0.f;

    // wait for conv grid (PDL) before touching its outputs
#if __CUDA_ARCH__ >= 900
    cudaGridDependencySynchronize();
#endif

    // p2 tile -> smem
    reinterpret_cast<float*>(smem + SM_P2)[tid] = g_p2[n0 + tid];

    // prologue: chunks 0,1 -> buffers 0,1
    #pragma unroll
    for (int pc = 0; pc < 2; pc++) {
        #pragma unroll
        for (int it = 0; it < 4; it++)
            cp16(sA0 + pc * TILE_A + it * (32 * 128), gA + pc * KC + (size_t)it * 32 * NFEAT);
        #pragma unroll
        for (int it = 0; it < 8; it++)
            cp16(sB0 + pc * TILE_BB + it * (32 * 128), gB + pc * KC + (size_t)it * 32 * NFEAT);
        asm volatile("cp.async.commit_group;" ::: "memory");
    }

    #pragma unroll 1
    for (int c = 0; c < NCHUNK; c++) {
        if (c < NCHUNK - 1) asm volatile("cp.async.wait_group 1;" ::: "memory");
        else                asm volatile("cp.async.wait_group 0;" ::: "memory");
        __syncthreads();

        // issue chunk c+2 into buffer (c+2)%3
        if (c + 2 < NCHUNK) {
            int nb = (c + 2) % 3;
            const __nv_bfloat16* gA2 = gA + (c + 2) * KC;
            const __nv_bfloat16* gB2 = gB + (c + 2) * KC;
            #pragma unroll
            for (int it = 0; it < 4; it++)
                cp16(sA0 + nb * TILE_A + it * (32 * 128), gA2 + (size_t)it * 32 * NFEAT);
            #pragma unroll
            for (int it = 0; it < 8; it++)
                cp16(sB0 + nb * TILE_BB + it * (32 * 128), gB2 + (size_t)it * 32 * NFEAT);
            asm volatile("cp.async.commit_group;" ::: "memory");
        }

        uint32_t bufA = sb + SM_A + (c % 3) * TILE_A;
        uint32_t bufB = sb + SM_B + (c % 3) * TILE_BB;

        #pragma unroll
        for (int ks = 0; ks < 4; ks++) {
            uint32_t afr[4][4], bfr[4][4];
            #pragma unroll
            for (int i = 0; i < 4; i++) {
                int r = a_rbase + i * 16;
                int ch = ks * 2 + a_chi;
                ldsm4(afr[i], bufA + r * 128 + ((ch ^ (r & 7)) << 4));
            }
            #pragma unroll
            for (int j2 = 0; j2 < 4; j2++) {
                int r = b_rbase + j2 * 16;
                int ch = ks * 2 + b_chi;
                ldsm4(bfr[j2], bufB + r * 128 + ((ch ^ (r & 7)) << 4));
            }
            #pragma unroll
            for (int i = 0; i < 4; i++)
                #pragma unroll
                for (int j = 0; j < 8; j++)
                    mma16816(acc[i][j], afr[i], bfr[j >> 1] + (j & 1) * 2);
        }
    }

    // ---- epilogue: per-(row,class) packed argmin, plain store ----
    const float* sp2 = reinterpret_cast<const float*>(smem + SM_P2);
    const int cls0 = (n0 >> 5) + wn * 2;
    const int colq = 2 * (lane & 3);

    float p2r[8][2];
    #pragma unroll
    for (int j = 0; j < 8; j++) {
        p2r[j][0] = sp2[wn * 64 + j * 8 + colq];
        p2r[j][1] = sp2[wn * 64 + j * 8 + colq + 1];
    }

    #pragma unroll
    for (int i = 0; i < 4; i++) {
        #pragma unroll
        for (int h = 0; h < 2; h++) {          // class within warp tile
            unsigned long long plo = ~0ull, phi = ~0ull;
            #pragma unroll
            for (int q = 0; q < 4; q++) {
                int j = h * 4 + q;
                #pragma unroll
                for (int t = 0; t < 2; t++) {
                    unsigned nidx = (unsigned)(n0 + wn * 64 + j * 8 + colq + t);
                    float p2v = p2r[j][t];
                    float slo = p2v - 2.0f * acc[i][j][t];
                    plo = umin64(plo, ((unsigned long long)f2ord(slo) << 32) | nidx);
                    float shi = p2v - 2.0f * acc[i][j][2 + t];
                    phi = umin64(phi, ((unsigned long long)f2ord(shi) << 32) | nidx);
                }
            }
            #pragma unroll
            for (int o = 1; o <= 2; o <<= 1) {
                plo = umin64(plo, __shfl_xor_sync(0xffffffffu, plo, o));
                phi = umin64(phi, __shfl_xor_sync(0xffffffffu, phi, o));
            }
            if ((lane & 3) == 0) {
                int row = m0 + wm * 64 + i * 16 + (lane >> 2);
                g_minpack[(size_t)row * NCLS + cls0 + h] = plo;
                g_minpack[(size_t)(row + 8) * NCLS + cls0 + h] = phi;
            }
        }
    }
}

// ---------------- selection + fused final reduction (PDL) ----------------
__global__ __launch_bounds__(256) void select_kernel(const float* __restrict__ X,
                                                     const float* __restrict__ W,
                                                     const int* __restrict__ tgt,
                                                     float* __restrict__ out) {
    const int lane = threadIdx.x & 31;
    const int w = threadIdx.x >> 5;
    const int row = blockIdx.x * 8 + w;

    // independent load (input tensor, not produced by dist) + index math
    const int target = tgt[row];
    const unsigned long long* mp = g_minpack + (size_t)row * NCLS;

    // wait for dist grid (PDL) before reading minpack
#if __CUDA_ARCH__ >= 900
    cudaGridDependencySynchronize();
#endif

    unsigned long long best = ~0ull, tpk = ~0ull;
    #pragma unroll
    for (int c = lane; c < NCLS; c += 32) {
        unsigned long long v = mp[c];
        if (c == target) tpk = v;
        else best = umin64(best, v);
    }
    #pragma unroll
    for (int o = 16; o; o >>= 1) {
        best = umin64(best, __shfl_xor_sync(0xffffffffu, best, o));
        tpk  = umin64(tpk,  __shfl_xor_sync(0xffffffffu, tpk,  o));
    }

    int actual_n = (int)(unsigned)(tpk & 0xffffffffull);
    int wrong_n  = (int)(unsigned)(best & 0xffffffffull);

    const float4* xa = reinterpret_cast<const float4*>(X + (size_t)row * NFEAT);
    const float4* pa = reinterpret_cast<const float4*>(W + (size_t)actual_n * NFEAT);
    const float4* pw = reinterpret_cast<const float4*>(W + (size_t)wrong_n  * NFEAT);
    float ts = 0.f, ws = 0.f;
    #pragma unroll
    for (int f = lane; f < NFEAT / 4; f += 32) {
        float4 x = xa[f], a = pa[f], b = pw[f];
        float d;
        d = x.x - a.x; ts += d * d;  d = x.y - a.y; ts += d * d;
        d = x.z - a.z; ts += d * d;  d = x.w - a.w; ts += d * d;
        d = x.x - b.x; ws += d * d;  d = x.y - b.y; ws += d * d;
        d = x.z - b.z; ws += d * d;  d = x.w - b.w; ws += d * d;
    }
    #pragma unroll
    for (int o = 16; o; o >>= 1) {
        ts += __shfl_xor_sync(0xffffffffu, ts, o);
        ws += __shfl_xor_sync(0xffffffffu, ws, o);
    }

    __shared__ float shf[2][8];
    if (lane == 0) { shf[0][w] = ts; shf[1][w] = ws; }
    __syncthreads();
    if (threadIdx.x == 0) {
        float a = 0.f, b = 0.f;
        #pragma unroll
        for (int i = 0; i < 8; i++) { a += shf[0][i]; b += shf[1][i]; }
        atomicAdd(&g_acc[0], a);
        atomicAdd(&g_acc[1], b);
        __threadfence();
        unsigned int ticket = atomicAdd(&g_done, 1u);
        if (ticket == SEL_BLOCKS - 1) {
            float tsum = *((volatile float*)&g_acc[0]);
            float wsum = *((volatile float*)&g_acc[1]);
            float denom = (float)BATCH * (float)NFEAT;
            float tl  = tsum / denom;
            float ntl = wsum / denom;
            out[0] = (1.0f - ALPHA_F) * tl + ALPHA_F * (1.0f / (ntl + EPS_F));
        }
    }
}

extern "C" void kernel_launch(void* const* d_in, const int* in_sizes, int n_in,
                              void* d_out, int out_size) {
    const float* X   = (const float*)d_in[0];   // outputs [4096, 512]
    const float* W   = (const float*)d_in[1];   // clusters [6400, 512]
    const int*   tgt = (const int*)d_in[2];     // target_classes [4096]
    float* out = (float*)d_out;

    cudaFuncSetAttribute(dist_kernel, cudaFuncAttributeMaxDynamicSharedMemorySize, SMEM_TOTAL);

    conv_kernel<<<CONV_WBLKS + CONV_XBLKS, 256>>>(X, W);

    // PDL attribute: allow overlap with predecessor's tail; the kernel itself
    // gates dependent loads via cudaGridDependencySynchronize().
    cudaLaunchAttribute pdl[1];
    pdl[0].id = cudaLaunchAttributeProgrammaticStreamSerialization;
    pdl[0].val.programmaticStreamSerializationAllowed = 1;

    {
        cudaLaunchConfig_t cfg = {};
        cfg.gridDim = dim3(NPROT / BN, BATCH / BM);   // (25, 32)
        cfg.blockDim = dim3(256);
        cfg.dynamicSmemBytes = SMEM_TOTAL;
        cfg.attrs = pdl;
        cfg.numAttrs = 1;
        cudaLaunchKernelEx(&cfg, dist_kernel);
    }
    {
        cudaLaunchConfig_t cfg = {};
        cfg.gridDim = dim3(SEL_BLOCKS);
        cfg.blockDim = dim3(256);
        cfg.attrs = pdl;
        cfg.numAttrs = 1;
        cudaLaunchKernelEx(&cfg, select_kernel, X, W, tgt, out);
    }
}